// round 16
// baseline (speedup 1.0000x reference)
#include <cuda_runtime.h>
#include <cuda_bf16.h>
#include <cuda_pipeline.h>
#include <mma.h>
#include <cstdint>

using namespace nvcuda;

// Problem constants (fixed by dataset)
#define DFEAT 512
#define NOUT  64
#define GROWS 96              // gemm rows per block
#define MAXN  100032          // N_NODES rounded up: divisible by 96 (96*1042)
#define NPAD  102400          // node arrays padded to 1024*100 for scan tiles
#define MAXE  1600000
#define NBLK_SCAN 100         // NPAD / 1024
#define WSPLIT_BLKS 128       // 32768 W elements / 256

// Static device scratch (no runtime allocation allowed).
// INVARIANT: g_cnt and g_tilestate are ZERO at entry of every call — they are
// zero-initialized at module load, and every call re-zeros them in the fused
// kernel (slot 3) after scan (their last reader) is done. Deterministic.
__device__ float          g_h[(size_t)MAXN * NOUT];   // projected features (25.6 MB)
__device__ __nv_bfloat16  g_Wh16[DFEAT * NOUT];       // W hi bf16, [k][n]
__device__ __nv_bfloat16  g_Wl16[DFEAT * NOUT];       // W lo residual bf16, [k][n]
__device__ uint2          g_pairs[MAXE];              // (src, w-bits) grouped by dst
__device__ int            g_cnt[NPAD];                // per-dst degree
__device__ int            g_start[NPAD];              // CSR row start
__device__ int            g_cursor[NPAD];             // fill cursor == row end
__device__ unsigned int   g_tilestate[NBLK_SCAN];     // lookback: flag<<30 | sum

// ---------------------------------------------------------------------------
// Slot 1: fused W-split + dst-degree histogram (independent works, one launch)
// ---------------------------------------------------------------------------
__global__ void __launch_bounds__(256) setup_hist_kernel(const float* __restrict__ W,
                                                         const int*   __restrict__ edst,
                                                         int n_edges)
{
    if (blockIdx.x < WSPLIT_BLKS) {
        int i = blockIdx.x * 256 + threadIdx.x;          // < 32768 always
        float w = __ldg(&W[i]);
        uint32_t u = __float_as_uint(w);
        unsigned short hb = (unsigned short)(u >> 16);   // truncated bf16
        g_Wh16[i] = *reinterpret_cast<__nv_bfloat16*>(&hb);
        float lo = w - __uint_as_float(u & 0xFFFF0000u);
        g_Wl16[i] = __float2bfloat16_rn(lo);
    } else {
        int t = (blockIdx.x - WSPLIT_BLKS) * 256 + threadIdx.x;
        int e = t * 4;
        if (e + 3 < n_edges) {
            int4 d = *(const int4*)(edst + e);
            atomicAdd(&g_cnt[d.x], 1);
            atomicAdd(&g_cnt[d.y], 1);
            atomicAdd(&g_cnt[d.z], 1);
            atomicAdd(&g_cnt[d.w], 1);
        } else {
            for (int k = e; k < n_edges; ++k) atomicAdd(&g_cnt[__ldg(&edst[k])], 1);
        }
    }
}

// ---------------------------------------------------------------------------
// Slot 2: single-pass exclusive scan (decoupled lookback), 1024 nodes/block.
// ---------------------------------------------------------------------------
__global__ void __launch_bounds__(256) scan_onepass_kernel() {
    const int b   = blockIdx.x;
    const int tid = threadIdx.x;
    const int idx = b * 1024 + tid * 4;

    int4 c = *(const int4*)&g_cnt[idx];
    int t = c.x + c.y + c.z + c.w;

    int incl = t;
#pragma unroll
    for (int o = 1; o < 32; o <<= 1) {
        int u = __shfl_up_sync(0xffffffffu, incl, o);
        if ((tid & 31) >= o) incl += u;
    }
    __shared__ int wsum[8];
    __shared__ int s_excl;
    if ((tid & 31) == 31) wsum[tid >> 5] = incl;
    __syncthreads();

    const int wid = tid >> 5;
    int off = 0, agg = 0;
#pragma unroll
    for (int i = 0; i < 8; ++i) {
        int v = wsum[i];
        if (i < wid) off += v;
        agg += v;
    }

    if (tid == 0) {
        if (b == 0) {
            atomicExch(&g_tilestate[0], (2u << 30) | (unsigned)agg);
            s_excl = 0;
        } else {
            atomicExch(&g_tilestate[b], (1u << 30) | (unsigned)agg);
            int run = 0, p = b - 1;
            while (true) {
                unsigned s;
                do { s = atomicAdd(&g_tilestate[p], 0u); } while ((s >> 30) == 0u);
                run += (int)(s & 0x3fffffffu);
                if ((s >> 30) == 2u) break;
                --p;
            }
            atomicExch(&g_tilestate[b], (2u << 30) | (unsigned)(run + agg));
            s_excl = run;
        }
    }
    __syncthreads();

    int s0 = s_excl + (incl - t) + off;
    int4 st;
    st.x = s0; st.y = s0 + c.x; st.z = st.y + c.y; st.w = st.z + c.z;
    *(int4*)&g_start[idx]  = st;
    *(int4*)&g_cursor[idx] = st;
}

// ---------------------------------------------------------------------------
// pack2: (f0,f1) -> packed bf16x2 hi (truncated, via PRMT) + bf16x2 lo
// ---------------------------------------------------------------------------
__device__ __forceinline__ void pack2(float f0, float f1, uint32_t& hp, uint32_t& lp) {
    uint32_t u0 = __float_as_uint(f0), u1 = __float_as_uint(f1);
    hp = __byte_perm(u0, u1, 0x7632);                 // (hi16(f0), hi16(f1))
    float l0 = f0 - __uint_as_float(u0 & 0xFFFF0000u);
    float l1 = f1 - __uint_as_float(u1 & 0xFFFF0000u);
    __nv_bfloat162 l2 = __floats2bfloat162_rn(l0, l1);
    lp = *reinterpret_cast<uint32_t*>(&l2);
}

// ---------------------------------------------------------------------------
// Slot 3: FUSED gemm + reorder + state-reset by blockIdx range. (R15 config)
// ---------------------------------------------------------------------------
__global__ void __launch_bounds__(192, 3) fused_kernel(const float* __restrict__ x,
                                                       const int*   __restrict__ esrc,
                                                       const int*   __restrict__ edst,
                                                       const float* __restrict__ ew,
                                                       int n_rows, int n_edges,
                                                       int ngemm, int nreo)
{
    if (blockIdx.x >= ngemm) {
        int rb = blockIdx.x - ngemm;
        if (rb < nreo) {
            // ---- reorder: edges -> dst-grouped (src, w) pairs ----
            int t = rb * 192 + threadIdx.x;
            int e = t * 2;
            if (e + 1 < n_edges) {
                int2   s = *(const int2*)(esrc + e);
                int2   d = *(const int2*)(edst + e);
                float2 w = *(const float2*)(ew + e);
                int p0 = atomicAdd(&g_cursor[d.x], 1);
                g_pairs[p0] = make_uint2((unsigned)s.x, __float_as_uint(w.x));
                int p1 = atomicAdd(&g_cursor[d.y], 1);
                g_pairs[p1] = make_uint2((unsigned)s.y, __float_as_uint(w.y));
            } else if (e < n_edges) {
                int d = __ldg(&edst[e]);
                int pos = atomicAdd(&g_cursor[d], 1);
                g_pairs[pos] = make_uint2((unsigned)__ldg(&esrc[e]),
                                          __float_as_uint(__ldg(&ew[e])));
            }
        } else {
            // ---- reset g_cnt / g_tilestate for the next call (scan is done) ----
            int idx = (rb - nreo) * 192 + threadIdx.x;
            if (idx < NPAD / 4) ((int4*)g_cnt)[idx] = make_int4(0, 0, 0, 0);
            if (idx < NBLK_SCAN) g_tilestate[idx] = 0u;
        }
        return;
    }

    // ---- GEMM body (R11 config: 96x64 tile, split-bf16 HMMA, 3 CTAs/SM) ----
    __shared__ __align__(16) __nv_bfloat16 xs_hi[GROWS][40];
    __shared__ __align__(16) __nv_bfloat16 xs_lo[GROWS][40];
    __shared__ __align__(16) __nv_bfloat16 ws_hi[32][72];
    __shared__ __align__(16) __nv_bfloat16 ws_lo[32][72];

    const int tid  = threadIdx.x;
    const int row0 = blockIdx.x * GROWS;

    const int wid    = tid >> 5;
    const int warp_r = (wid >> 1) * 32;   // 0,32,64
    const int warp_c = (wid & 1) * 32;    // 0,32

    wmma::fragment<wmma::accumulator, 16, 16, 16, float> acc[2][2];
#pragma unroll
    for (int i = 0; i < 2; ++i)
#pragma unroll
        for (int j = 0; j < 2; ++j)
            wmma::fill_fragment(acc[i][j], 0.0f);

    float4 xv[4];
    int  xrow[4];
#pragma unroll
    for (int p = 0; p < 4; ++p) {
        int f = tid + p * 192;
        int r = f >> 3;
        int gr = row0 + r;
        if (gr >= n_rows) gr = n_rows - 1;           // clamp: dup rows, never gathered
        xrow[p] = gr;
        xv[p] = *(const float4*)(x + (size_t)gr * DFEAT + (f & 7) * 4);
    }

    const int KT = DFEAT / 32;
    for (int kt = 0; kt < KT; ++kt) {
#pragma unroll
        for (int p = 0; p < 4; ++p) {
            int f = tid + p * 192;
            int r = f >> 3;
            int k4 = (f & 7) * 4;
            uint32_t h0, l0, h1, l1;
            pack2(xv[p].x, xv[p].y, h0, l0);
            pack2(xv[p].z, xv[p].w, h1, l1);
            *(uint2*)&xs_hi[r][k4] = make_uint2(h0, h1);
            *(uint2*)&xs_lo[r][k4] = make_uint2(l0, l1);
        }
        for (int g = tid; g < 512; g += 192) {
            int hi = (g < 256);
            int gg = g & 255;
            int r  = gg >> 3;
            int c8 = (gg & 7) * 8;
            const __nv_bfloat16* src = (hi ? g_Wh16 : g_Wl16) + (size_t)(kt * 32 + r) * NOUT + c8;
            __nv_bfloat16* dst = (hi ? &ws_hi[r][c8] : &ws_lo[r][c8]);
            __pipeline_memcpy_async(dst, src, 16);
        }
        __pipeline_commit();

        if (kt + 1 < KT) {
#pragma unroll
            for (int p = 0; p < 4; ++p) {
                int f = tid + p * 192;
                xv[p] = *(const float4*)(x + (size_t)xrow[p] * DFEAT + (kt + 1) * 32 + (f & 7) * 4);
            }
        }

        __pipeline_wait_prior(0);
        __syncthreads();

#pragma unroll
        for (int ks = 0; ks < 2; ++ks) {
            const int k0 = ks * 16;
            wmma::fragment<wmma::matrix_a, 16, 16, 16, __nv_bfloat16, wmma::row_major> a_hi[2], a_lo[2];
#pragma unroll
            for (int i = 0; i < 2; ++i) {
                wmma::load_matrix_sync(a_hi[i], &xs_hi[warp_r + i * 16][k0], 40);
                wmma::load_matrix_sync(a_lo[i], &xs_lo[warp_r + i * 16][k0], 40);
            }
#pragma unroll
            for (int j = 0; j < 2; ++j) {
                wmma::fragment<wmma::matrix_b, 16, 16, 16, __nv_bfloat16, wmma::row_major> b_hi, b_lo;
                wmma::load_matrix_sync(b_hi, &ws_hi[k0][warp_c + j * 16], 72);
                wmma::load_matrix_sync(b_lo, &ws_lo[k0][warp_c + j * 16], 72);
#pragma unroll
                for (int i = 0; i < 2; ++i) {
                    wmma::mma_sync(acc[i][j], a_hi[i], b_hi, acc[i][j]);
                    wmma::mma_sync(acc[i][j], a_hi[i], b_lo, acc[i][j]);
                    wmma::mma_sync(acc[i][j], a_lo[i], b_hi, acc[i][j]);
                }
            }
        }
        __syncthreads();
    }

#pragma unroll
    for (int i = 0; i < 2; ++i)
#pragma unroll
        for (int j = 0; j < 2; ++j)
            wmma::store_matrix_sync(
                g_h + (size_t)(row0 + warp_r + i * 16) * NOUT + warp_c + j * 16,
                acc[i][j], NOUT, wmma::mem_row_major);
}

// ---------------------------------------------------------------------------
// Slot 4 (profiled): gather + fused softmax, 2 edges per iteration.
// Half-warp scheme: lanes 0-15 own all 64 channels (float4) for even edges,
// lanes 16-31 for odd edges; one variable-source shfl broadcasts each half's
// (src, w). Final xor-16 merge combines the two half-accumulators.
// Per 2 edges: 1 LDG.128 + 2 SHFL + 4 FFMA (was 2 LDG.64 + 4 SHFL + 4 FFMA).
// ---------------------------------------------------------------------------
__global__ void __launch_bounds__(256) gather_softmax_kernel(float* __restrict__ out,
                                                             int n_nodes)
{
    int node = blockIdx.x * 8 + (threadIdx.x >> 5);
    int lane = threadIdx.x & 31;
    if (node >= n_nodes) return;

    int start = __ldg(&g_start[node]);
    int end   = __ldg(&g_cursor[node]);

    const int half = lane >> 4;           // 0: even edges, 1: odd edges
    const int qc   = (lane & 15) << 2;    // channel base, 0..60

    float4 acc = make_float4(0.f, 0.f, 0.f, 0.f);

    for (int base = start; base < end; base += 32) {
        int idx = base + lane;
        uint2 pr = make_uint2(0u, 0u);
        if (idx < end) pr = __ldg(&g_pairs[idx]);
        int m = end - base; if (m > 32) m = 32;

        int j = 0;
        // 8 edges per unrolled step (4 iterations of the 2-edge scheme)
        for (; j + 8 <= m; j += 8) {
#pragma unroll
            for (int u = 0; u < 4; ++u) {
                int srcl = j + 2 * u + half;
                int   ss = __shfl_sync(0xffffffffu, (int)pr.x, srcl);
                float sw = __uint_as_float(__shfl_sync(0xffffffffu, pr.y, srcl));
                float4 hv = *(const float4*)(g_h + (size_t)ss * NOUT + qc);
                acc.x = fmaf(sw, hv.x, acc.x);
                acc.y = fmaf(sw, hv.y, acc.y);
                acc.z = fmaf(sw, hv.z, acc.z);
                acc.w = fmaf(sw, hv.w, acc.w);
            }
        }
        for (; j + 2 <= m; j += 2) {
            int srcl = j + half;
            int   ss = __shfl_sync(0xffffffffu, (int)pr.x, srcl);
            float sw = __uint_as_float(__shfl_sync(0xffffffffu, pr.y, srcl));
            float4 hv = *(const float4*)(g_h + (size_t)ss * NOUT + qc);
            acc.x = fmaf(sw, hv.x, acc.x);
            acc.y = fmaf(sw, hv.y, acc.y);
            acc.z = fmaf(sw, hv.z, acc.z);
            acc.w = fmaf(sw, hv.w, acc.w);
        }
        if (j < m) {   // odd tail: half 1 contributes 0 (weight masked)
            int   ss = __shfl_sync(0xffffffffu, (int)pr.x, j);
            float sw = __uint_as_float(__shfl_sync(0xffffffffu, pr.y, j));
            float swm = half ? 0.f : sw;
            float4 hv = *(const float4*)(g_h + (size_t)ss * NOUT + qc);
            acc.x = fmaf(swm, hv.x, acc.x);
            acc.y = fmaf(swm, hv.y, acc.y);
            acc.z = fmaf(swm, hv.z, acc.z);
            acc.w = fmaf(swm, hv.w, acc.w);
        }
    }

    // merge halves: lane i and i^16 hold the same channels
    acc.x += __shfl_xor_sync(0xffffffffu, acc.x, 16);
    acc.y += __shfl_xor_sync(0xffffffffu, acc.y, 16);
    acc.z += __shfl_xor_sync(0xffffffffu, acc.z, 16);
    acc.w += __shfl_xor_sync(0xffffffffu, acc.w, 16);

    // softmax over 64 channels (values replicated across halves -> xor 8..1)
    float mx = fmaxf(fmaxf(acc.x, acc.y), fmaxf(acc.z, acc.w));
#pragma unroll
    for (int o = 8; o > 0; o >>= 1)
        mx = fmaxf(mx, __shfl_xor_sync(0xffffffffu, mx, o));

    float e0 = __expf(acc.x - mx);
    float e1 = __expf(acc.y - mx);
    float e2 = __expf(acc.z - mx);
    float e3 = __expf(acc.w - mx);
    float s = (e0 + e1) + (e2 + e3);
#pragma unroll
    for (int o = 8; o > 0; o >>= 1)
        s += __shfl_xor_sync(0xffffffffu, s, o);

    float inv = 1.0f / s;
    if (half == 0)
        *(float4*)&out[(size_t)node * NOUT + qc] =
            make_float4(e0 * inv, e1 * inv, e2 * inv, e3 * inv);
}

// ---------------------------------------------------------------------------
// Launch. Input order per metadata: x, edge_src, edge_dst, edge_w, W.
// 4 launches: (Wsplit+hist) -> scan -> (gemm||reorder||zero) -> gather.
// ---------------------------------------------------------------------------
extern "C" void kernel_launch(void* const* d_in, const int* in_sizes, int n_in,
                              void* d_out, int out_size)
{
    const float* x    = (const float*)d_in[0];
    const int*   esrc = (const int*)  d_in[1];
    const int*   edst = (const int*)  d_in[2];
    const float* ew   = (const float*)d_in[3];
    const float* W    = (const float*)d_in[4];
    float*       out  = (float*)d_out;

    const int n_nodes = in_sizes[0] / DFEAT;
    const int n_edges = in_sizes[1];
    const int ntiles  = (n_nodes + 1023) / 1024;
    const int hblk    = (n_edges + 1023) / 1024;           // 4 edges/thread, 256 thr
    const int ngemm   = (n_nodes + GROWS - 1) / GROWS;     // 1042
    const int nreo    = (n_edges + 383) / 384;             // 2 edges/thread, 192 thr
    const int nzero   = (NPAD / 4 + 191) / 192;            // 134

    setup_hist_kernel<<<WSPLIT_BLKS + hblk, 256>>>(W, edst, n_edges);        // 1
    scan_onepass_kernel<<<ntiles, 256>>>();                                  // 2
    fused_kernel<<<ngemm + nreo + nzero, 192>>>(x, esrc, edst, ew,
                                                n_nodes, n_edges,
                                                ngemm, nreo);                // 3
    gather_softmax_kernel<<<(n_nodes + 7) / 8, 256>>>(out, n_nodes);         // 4 (profiled)
}

// round 17
// speedup vs baseline: 1.0815x; 1.0815x over previous
#include <cuda_runtime.h>
#include <cuda_bf16.h>
#include <cuda_pipeline.h>
#include <mma.h>
#include <cstdint>

using namespace nvcuda;

// Problem constants (fixed by dataset)
#define DFEAT 512
#define NOUT  64
#define GROWS 96              // gemm rows per block
#define MAXN  100032          // N_NODES rounded up: divisible by 96 (96*1042)
#define NPAD  102400          // node arrays padded to 1024*100 for scan tiles
#define MAXE  1600000
#define NBLK_SCAN 100         // NPAD / 1024
#define WSPLIT_BLKS 128       // 32768 W elements / 256

// Static device scratch (no runtime allocation allowed).
// INVARIANT: g_cnt and g_tilestate are ZERO at entry of every call — they are
// zero-initialized at module load, and every call re-zeros them in the fused
// kernel (slot 3) after scan (their last reader) is done. Deterministic.
__device__ float          g_h[(size_t)MAXN * NOUT];   // projected features (25.6 MB)
__device__ __nv_bfloat16  g_Wh16[DFEAT * NOUT];       // W hi bf16, [k][n]
__device__ __nv_bfloat16  g_Wl16[DFEAT * NOUT];       // W lo residual bf16, [k][n]
__device__ uint2          g_pairs[MAXE];              // (src, w-bits) grouped by dst
__device__ int            g_cnt[NPAD];                // per-dst degree
__device__ int            g_start[NPAD];              // CSR row start
__device__ int            g_cursor[NPAD];             // fill cursor == row end
__device__ unsigned int   g_tilestate[NBLK_SCAN];     // lookback: flag<<30 | sum

// ---------------------------------------------------------------------------
// Slot 1: fused W-split + dst-degree histogram (independent works, one launch)
// ---------------------------------------------------------------------------
__global__ void __launch_bounds__(256) setup_hist_kernel(const float* __restrict__ W,
                                                         const int*   __restrict__ edst,
                                                         int n_edges)
{
    if (blockIdx.x < WSPLIT_BLKS) {
        int i = blockIdx.x * 256 + threadIdx.x;          // < 32768 always
        float w = __ldg(&W[i]);
        uint32_t u = __float_as_uint(w);
        unsigned short hb = (unsigned short)(u >> 16);   // truncated bf16
        g_Wh16[i] = *reinterpret_cast<__nv_bfloat16*>(&hb);
        float lo = w - __uint_as_float(u & 0xFFFF0000u);
        g_Wl16[i] = __float2bfloat16_rn(lo);
    } else {
        int t = (blockIdx.x - WSPLIT_BLKS) * 256 + threadIdx.x;
        int e = t * 4;
        if (e + 3 < n_edges) {
            int4 d = *(const int4*)(edst + e);
            atomicAdd(&g_cnt[d.x], 1);
            atomicAdd(&g_cnt[d.y], 1);
            atomicAdd(&g_cnt[d.z], 1);
            atomicAdd(&g_cnt[d.w], 1);
        } else {
            for (int k = e; k < n_edges; ++k) atomicAdd(&g_cnt[__ldg(&edst[k])], 1);
        }
    }
}

// ---------------------------------------------------------------------------
// Slot 2: single-pass exclusive scan (decoupled lookback), 1024 nodes/block.
// ---------------------------------------------------------------------------
__global__ void __launch_bounds__(256) scan_onepass_kernel() {
    const int b   = blockIdx.x;
    const int tid = threadIdx.x;
    const int idx = b * 1024 + tid * 4;

    int4 c = *(const int4*)&g_cnt[idx];
    int t = c.x + c.y + c.z + c.w;

    int incl = t;
#pragma unroll
    for (int o = 1; o < 32; o <<= 1) {
        int u = __shfl_up_sync(0xffffffffu, incl, o);
        if ((tid & 31) >= o) incl += u;
    }
    __shared__ int wsum[8];
    __shared__ int s_excl;
    if ((tid & 31) == 31) wsum[tid >> 5] = incl;
    __syncthreads();

    const int wid = tid >> 5;
    int off = 0, agg = 0;
#pragma unroll
    for (int i = 0; i < 8; ++i) {
        int v = wsum[i];
        if (i < wid) off += v;
        agg += v;
    }

    if (tid == 0) {
        if (b == 0) {
            atomicExch(&g_tilestate[0], (2u << 30) | (unsigned)agg);
            s_excl = 0;
        } else {
            atomicExch(&g_tilestate[b], (1u << 30) | (unsigned)agg);
            int run = 0, p = b - 1;
            while (true) {
                unsigned s;
                do { s = atomicAdd(&g_tilestate[p], 0u); } while ((s >> 30) == 0u);
                run += (int)(s & 0x3fffffffu);
                if ((s >> 30) == 2u) break;
                --p;
            }
            atomicExch(&g_tilestate[b], (2u << 30) | (unsigned)(run + agg));
            s_excl = run;
        }
    }
    __syncthreads();

    int s0 = s_excl + (incl - t) + off;
    int4 st;
    st.x = s0; st.y = s0 + c.x; st.z = st.y + c.y; st.w = st.z + c.z;
    *(int4*)&g_start[idx]  = st;
    *(int4*)&g_cursor[idx] = st;
}

// ---------------------------------------------------------------------------
// pack2: (f0,f1) -> packed bf16x2 hi (truncated, via PRMT) + bf16x2 lo
// ---------------------------------------------------------------------------
__device__ __forceinline__ void pack2(float f0, float f1, uint32_t& hp, uint32_t& lp) {
    uint32_t u0 = __float_as_uint(f0), u1 = __float_as_uint(f1);
    hp = __byte_perm(u0, u1, 0x7632);                 // (hi16(f0), hi16(f1))
    float l0 = f0 - __uint_as_float(u0 & 0xFFFF0000u);
    float l1 = f1 - __uint_as_float(u1 & 0xFFFF0000u);
    __nv_bfloat162 l2 = __floats2bfloat162_rn(l0, l1);
    lp = *reinterpret_cast<uint32_t*>(&l2);
}

// ---------------------------------------------------------------------------
// Slot 3: FUSED gemm + reorder + state-reset by blockIdx range. (R15 config)
// ---------------------------------------------------------------------------
__global__ void __launch_bounds__(192, 3) fused_kernel(const float* __restrict__ x,
                                                       const int*   __restrict__ esrc,
                                                       const int*   __restrict__ edst,
                                                       const float* __restrict__ ew,
                                                       int n_rows, int n_edges,
                                                       int ngemm, int nreo)
{
    if (blockIdx.x >= ngemm) {
        int rb = blockIdx.x - ngemm;
        if (rb < nreo) {
            // ---- reorder: edges -> dst-grouped (src, w) pairs ----
            int t = rb * 192 + threadIdx.x;
            int e = t * 2;
            if (e + 1 < n_edges) {
                int2   s = *(const int2*)(esrc + e);
                int2   d = *(const int2*)(edst + e);
                float2 w = *(const float2*)(ew + e);
                int p0 = atomicAdd(&g_cursor[d.x], 1);
                g_pairs[p0] = make_uint2((unsigned)s.x, __float_as_uint(w.x));
                int p1 = atomicAdd(&g_cursor[d.y], 1);
                g_pairs[p1] = make_uint2((unsigned)s.y, __float_as_uint(w.y));
            } else if (e < n_edges) {
                int d = __ldg(&edst[e]);
                int pos = atomicAdd(&g_cursor[d], 1);
                g_pairs[pos] = make_uint2((unsigned)__ldg(&esrc[e]),
                                          __float_as_uint(__ldg(&ew[e])));
            }
        } else {
            // ---- reset g_cnt / g_tilestate for the next call (scan is done) ----
            int idx = (rb - nreo) * 192 + threadIdx.x;
            if (idx < NPAD / 4) ((int4*)g_cnt)[idx] = make_int4(0, 0, 0, 0);
            if (idx < NBLK_SCAN) g_tilestate[idx] = 0u;
        }
        return;
    }

    // ---- GEMM body (R11 config: 96x64 tile, split-bf16 HMMA, 3 CTAs/SM) ----
    __shared__ __align__(16) __nv_bfloat16 xs_hi[GROWS][40];
    __shared__ __align__(16) __nv_bfloat16 xs_lo[GROWS][40];
    __shared__ __align__(16) __nv_bfloat16 ws_hi[32][72];
    __shared__ __align__(16) __nv_bfloat16 ws_lo[32][72];

    const int tid  = threadIdx.x;
    const int row0 = blockIdx.x * GROWS;

    const int wid    = tid >> 5;
    const int warp_r = (wid >> 1) * 32;   // 0,32,64
    const int warp_c = (wid & 1) * 32;    // 0,32

    wmma::fragment<wmma::accumulator, 16, 16, 16, float> acc[2][2];
#pragma unroll
    for (int i = 0; i < 2; ++i)
#pragma unroll
        for (int j = 0; j < 2; ++j)
            wmma::fill_fragment(acc[i][j], 0.0f);

    float4 xv[4];
    int  xrow[4];
#pragma unroll
    for (int p = 0; p < 4; ++p) {
        int f = tid + p * 192;
        int r = f >> 3;
        int gr = row0 + r;
        if (gr >= n_rows) gr = n_rows - 1;           // clamp: dup rows, never gathered
        xrow[p] = gr;
        xv[p] = *(const float4*)(x + (size_t)gr * DFEAT + (f & 7) * 4);
    }

    const int KT = DFEAT / 32;
    for (int kt = 0; kt < KT; ++kt) {
#pragma unroll
        for (int p = 0; p < 4; ++p) {
            int f = tid + p * 192;
            int r = f >> 3;
            int k4 = (f & 7) * 4;
            uint32_t h0, l0, h1, l1;
            pack2(xv[p].x, xv[p].y, h0, l0);
            pack2(xv[p].z, xv[p].w, h1, l1);
            *(uint2*)&xs_hi[r][k4] = make_uint2(h0, h1);
            *(uint2*)&xs_lo[r][k4] = make_uint2(l0, l1);
        }
        for (int g = tid; g < 512; g += 192) {
            int hi = (g < 256);
            int gg = g & 255;
            int r  = gg >> 3;
            int c8 = (gg & 7) * 8;
            const __nv_bfloat16* src = (hi ? g_Wh16 : g_Wl16) + (size_t)(kt * 32 + r) * NOUT + c8;
            __nv_bfloat16* dst = (hi ? &ws_hi[r][c8] : &ws_lo[r][c8]);
            __pipeline_memcpy_async(dst, src, 16);
        }
        __pipeline_commit();

        if (kt + 1 < KT) {
#pragma unroll
            for (int p = 0; p < 4; ++p) {
                int f = tid + p * 192;
                xv[p] = *(const float4*)(x + (size_t)xrow[p] * DFEAT + (kt + 1) * 32 + (f & 7) * 4);
            }
        }

        __pipeline_wait_prior(0);
        __syncthreads();

#pragma unroll
        for (int ks = 0; ks < 2; ++ks) {
            const int k0 = ks * 16;
            wmma::fragment<wmma::matrix_a, 16, 16, 16, __nv_bfloat16, wmma::row_major> a_hi[2], a_lo[2];
#pragma unroll
            for (int i = 0; i < 2; ++i) {
                wmma::load_matrix_sync(a_hi[i], &xs_hi[warp_r + i * 16][k0], 40);
                wmma::load_matrix_sync(a_lo[i], &xs_lo[warp_r + i * 16][k0], 40);
            }
#pragma unroll
            for (int j = 0; j < 2; ++j) {
                wmma::fragment<wmma::matrix_b, 16, 16, 16, __nv_bfloat16, wmma::row_major> b_hi, b_lo;
                wmma::load_matrix_sync(b_hi, &ws_hi[k0][warp_c + j * 16], 72);
                wmma::load_matrix_sync(b_lo, &ws_lo[k0][warp_c + j * 16], 72);
#pragma unroll
                for (int i = 0; i < 2; ++i) {
                    wmma::mma_sync(acc[i][j], a_hi[i], b_hi, acc[i][j]);
                    wmma::mma_sync(acc[i][j], a_hi[i], b_lo, acc[i][j]);
                    wmma::mma_sync(acc[i][j], a_lo[i], b_hi, acc[i][j]);
                }
            }
        }
        __syncthreads();
    }

#pragma unroll
    for (int i = 0; i < 2; ++i)
#pragma unroll
        for (int j = 0; j < 2; ++j)
            wmma::store_matrix_sync(
                g_h + (size_t)(row0 + warp_r + i * 16) * NOUT + warp_c + j * 16,
                acc[i][j], NOUT, wmma::mem_row_major);
}

// ---------------------------------------------------------------------------
// Slot 4 (profiled): gather + fused softmax — R15 structure (float2/lane,
// one warp per node, occ-friendly) with the SHFL broadcast replaced by an
// LDS.64 broadcast from a per-warp smem staging buffer (256B/warp).
// Per edge: 1 LDS.64 + 1 LDG.64 + 2 FFMA (was 2 SHFL + 1 LDG.64 + 2 FFMA).
// ---------------------------------------------------------------------------
__global__ void __launch_bounds__(256) gather_softmax_kernel(float* __restrict__ out,
                                                             int n_nodes)
{
    __shared__ __align__(16) uint2 sp[8][32];   // per-warp pair staging (2KB)

    const int wslot = threadIdx.x >> 5;
    const int lane  = threadIdx.x & 31;
    int node = blockIdx.x * 8 + wslot;
    if (node >= n_nodes) return;

    int start = __ldg(&g_start[node]);
    int end   = __ldg(&g_cursor[node]);

    float2 acc = make_float2(0.f, 0.f);

    for (int base = start; base < end; base += 32) {
        int idx = base + lane;
        uint2 pr = make_uint2(0u, 0u);
        if (idx < end) pr = __ldg(&g_pairs[idx]);
        __syncwarp();                       // previous chunk's LDS reads done
        sp[wslot][lane] = pr;
        __syncwarp();                       // staging visible to whole warp

        int m = end - base; if (m > 32) m = 32;

        int j = 0;
        for (; j + 8 <= m; j += 8) {
#pragma unroll
            for (int u = 0; u < 8; ++u) {
                uint2 p = sp[wslot][j + u];              // LDS.64 broadcast
                float sw = __uint_as_float(p.y);
                float2 hv = *(const float2*)(g_h + (size_t)p.x * NOUT + (lane << 1));
                acc.x = fmaf(sw, hv.x, acc.x);
                acc.y = fmaf(sw, hv.y, acc.y);
            }
        }
        for (; j < m; ++j) {
            uint2 p = sp[wslot][j];
            float sw = __uint_as_float(p.y);
            float2 hv = *(const float2*)(g_h + (size_t)p.x * NOUT + (lane << 1));
            acc.x = fmaf(sw, hv.x, acc.x);
            acc.y = fmaf(sw, hv.y, acc.y);
        }
    }

    float mx = fmaxf(acc.x, acc.y);
#pragma unroll
    for (int o = 16; o > 0; o >>= 1)
        mx = fmaxf(mx, __shfl_xor_sync(0xffffffffu, mx, o));

    float e0 = __expf(acc.x - mx);
    float e1 = __expf(acc.y - mx);
    float s = e0 + e1;
#pragma unroll
    for (int o = 16; o > 0; o >>= 1)
        s += __shfl_xor_sync(0xffffffffu, s, o);

    float inv = 1.0f / s;
    *(float2*)&out[(size_t)node * NOUT + (lane << 1)] = make_float2(e0 * inv, e1 * inv);
}

// ---------------------------------------------------------------------------
// Launch. Input order per metadata: x, edge_src, edge_dst, edge_w, W.
// 4 launches: (Wsplit+hist) -> scan -> (gemm||reorder||zero) -> gather.
// ---------------------------------------------------------------------------
extern "C" void kernel_launch(void* const* d_in, const int* in_sizes, int n_in,
                              void* d_out, int out_size)
{
    const float* x    = (const float*)d_in[0];
    const int*   esrc = (const int*)  d_in[1];
    const int*   edst = (const int*)  d_in[2];
    const float* ew   = (const float*)d_in[3];
    const float* W    = (const float*)d_in[4];
    float*       out  = (float*)d_out;

    const int n_nodes = in_sizes[0] / DFEAT;
    const int n_edges = in_sizes[1];
    const int ntiles  = (n_nodes + 1023) / 1024;
    const int hblk    = (n_edges + 1023) / 1024;           // 4 edges/thread, 256 thr
    const int ngemm   = (n_nodes + GROWS - 1) / GROWS;     // 1042
    const int nreo    = (n_edges + 383) / 384;             // 2 edges/thread, 192 thr
    const int nzero   = (NPAD / 4 + 191) / 192;            // 134

    setup_hist_kernel<<<WSPLIT_BLKS + hblk, 256>>>(W, edst, n_edges);        // 1
    scan_onepass_kernel<<<ntiles, 256>>>();                                  // 2
    fused_kernel<<<ngemm + nreo + nzero, 192>>>(x, esrc, edst, ew,
                                                n_nodes, n_edges,
                                                ngemm, nreo);                // 3
    gather_softmax_kernel<<<(n_nodes + 7) / 8, 256>>>(out, n_nodes);         // 4 (profiled)
}